// round 11
// baseline (speedup 1.0000x reference)
#include <cuda_runtime.h>
#include <cstdint>

typedef unsigned long long ull;

#define Bb 2048
#define Tt 1000
#define Ii 40
#define Hh 16
#define TS 20
#define NCH (Tt/TS)
#define PADF 8
#define BSTR (TS*Ii + PADF)     /* 808 floats per batch-sub slot (16B aligned) */
#define BUFF (2*BSTR)           /* per-buffer floats (2 batch elems) */
#define CHBYTES (TS*Ii*4)       /* 3200B per batch per chunk */

// -------- device-global scratch (no allocation allowed) --------
__device__ float4 g_wpack[Hh*20];     // pre-scaled: branch0 pair *(oma*omb0), branch1 pair *(oma*omb1)
__device__ float  g_alpha[Hh];
__device__ float2 g_beta[Hh];
__device__ float2 g_w2[Hh];           // (W2[0][h], W2[1][h])
__device__ float2 g_b2c;
__device__ uint32_t g_masks[(Bb/2)*Tt];   // per-warp 32-bit spike masks (low16 = b0, high16 = b0+1)

// -------- packed f32x2 helpers --------
__device__ __forceinline__ ull pk2(float a, float b){ ull r; asm("mov.b64 %0,{%1,%2};":"=l"(r):"f"(a),"f"(b)); return r; }
__device__ __forceinline__ void upk2(ull v, float&a, float&b){ asm("mov.b64 {%0,%1},%2;":"=f"(a),"=f"(b):"l"(v)); }
__device__ __forceinline__ ull fma2(ull a, ull b, ull c){ ull d; asm("fma.rn.f32x2 %0,%1,%2,%3;":"=l"(d):"l"(a),"l"(b),"l"(c)); return d; }
__device__ __forceinline__ ull mul2(ull a, ull b){ ull d; asm("mul.rn.f32x2 %0,%1,%2;":"=l"(d):"l"(a),"l"(b)); return d; }
__device__ __forceinline__ ull add2(ull a, ull b){ ull d; asm("add.rn.f32x2 %0,%1,%2;":"=l"(d):"l"(a),"l"(b)); return d; }
// non-volatile: allow ptxas to schedule loads across steps
__device__ __forceinline__ void lds128(uint32_t a, ull&u, ull&v){ asm("ld.shared.v2.b64 {%0,%1},[%2];":"=l"(u),"=l"(v):"r"(a)); }
// -------- TMA bulk copy + mbarrier --------
__device__ __forceinline__ void bulkcp(uint32_t dst, const void* src, uint32_t bytes, uint32_t bar){
  asm volatile("cp.async.bulk.shared::cta.global.mbarrier::complete_tx::bytes [%0],[%1],%2,[%3];"
               :: "r"(dst), "l"(src), "r"(bytes), "r"(bar) : "memory");
}
__device__ __forceinline__ void mbar_init(uint32_t bar, uint32_t cnt){
  asm volatile("mbarrier.init.shared.b64 [%0],%1;" :: "r"(bar), "r"(cnt) : "memory");
}
__device__ __forceinline__ void mbar_expect_tx(uint32_t bar, uint32_t bytes){
  asm volatile("mbarrier.arrive.expect_tx.shared.b64 _,[%0],%1;" :: "r"(bar), "r"(bytes) : "memory");
}
__device__ __forceinline__ void mbar_wait(uint32_t bar, uint32_t parity){
  uint32_t done;
  asm volatile("{\n\t.reg .pred p;\n\t"
               "mbarrier.try_wait.parity.acquire.cta.shared::cta.b64 p,[%1],%2;\n\t"
               "selp.b32 %0,1,0,p;\n\t}"
               : "=r"(done) : "r"(bar), "r"(parity) : "memory");
  if (!done){
    asm volatile("{\n\t.reg .pred P1;\n\t"
                 "WL_%=:\n\t"
                 "mbarrier.try_wait.parity.acquire.cta.shared::cta.b64 P1,[%0],%1,0x989680;\n\t"
                 "@P1 bra.uni WD_%=;\n\t"
                 "bra.uni WL_%=;\n\t"
                 "WD_%=:\n\t}"
                 :: "r"(bar), "r"(parity) : "memory");
  }
}

// ---------------- init: scalar outputs ----------------
__global__ void init_kernel(float* __restrict__ out, long long corrIdx, long long totIdx){
  if (threadIdx.x == 0){
    out[0] = 0.0f;
    out[corrIdx] = 0.0f;
    int cnt = 0;
    for (int t=0;t<Tt;t++) cnt += ((t>10) && (((t-10)%15)>5)) ? 1 : 0;
    out[totIdx] = (float)cnt * (float)Bb;   // flags.sum() * B
  }
}

// ---------------- pack: pre-scale weights (parallel) ----------------
__global__ void pack_kernel(const float* __restrict__ W1, const float* __restrict__ tau_m,
                            const float* __restrict__ tau_n, const float* __restrict__ mask,
                            const float* __restrict__ W2, const float* __restrict__ b2){
  int tid = threadIdx.x;                    // 320 threads: (h, k) pairs
  if (tid < Hh*20){
    int h = tid / 20, k = tid % 20;
    float a = 1.0f/(1.0f + expf(-tau_m[h]));
    float oma = 1.0f - a;
    float be0 = 1.0f/(1.0f+expf(-tau_n[h*2+0]));
    float be1 = 1.0f/(1.0f+expf(-tau_n[h*2+1]));
    float s0 = oma*(1.0f-be0);
    float s1 = oma*(1.0f-be1);
    int r0 = (2*h)*Ii, r1 = (2*h+1)*Ii;
    float4 w;
    w.x = W1[r0+2*k]  *mask[r0+2*k]  *s0;
    w.y = W1[r0+2*k+1]*mask[r0+2*k+1]*s0;
    w.z = W1[r1+2*k]  *mask[r1+2*k]  *s1;
    w.w = W1[r1+2*k+1]*mask[r1+2*k+1]*s1;
    g_wpack[h*20+k] = w;
    if (k == 0){
      g_alpha[h] = a;
      g_beta[h]  = make_float2(be0, be1);
      g_w2[h]    = make_float2(W2[h], W2[Hh+h]);
    }
  }
  if (tid == 0) g_b2c = make_float2(b2[0], b2[1]);
}

// ---------------- main: sequential SNN recurrence, warp = 2 batch x 16 neurons ----------------
// Identical to the 188.9us kernel EXCEPT: per-step ballot + predicated STG (with memory
// clobber) replaced by register bit-accumulation + one 20-ballot transpose per chunk.
__global__ void __launch_bounds__(32) snn_kernel(const float* __restrict__ x){
  __shared__ __align__(16) float sx[2*BUFF];
  __shared__ __align__(8) ull smbar[2];
  const int lane = threadIdx.x;
  const int bsub = lane >> 4;
  const int h    = lane & 15;
  const int b0   = blockIdx.x * 2;

  ull wa[20], wb[20];
  #pragma unroll
  for (int k=0;k<20;k++){ float4 w = g_wpack[h*20+k]; wa[k]=pk2(w.x,w.y); wb[k]=pk2(w.z,w.w); }
  const float alpha = g_alpha[h];
  const float2 bt  = g_beta[h];

  float d0=0.f, d1=0.f, mem=0.f;
  float asel = 0.f;                 // alpha if previous spike else 0 (computed off-path)
  uint32_t sbase = (uint32_t)__cvta_generic_to_shared(sx);
  uint32_t barb  = (uint32_t)__cvta_generic_to_shared(smbar);

  uint32_t* mrow = g_masks + (size_t)blockIdx.x * Tt;

  const float* xg0 = x + (size_t)b0     * Tt * Ii;
  const float* xg1 = x + (size_t)(b0+1) * Tt * Ii;

  // init barriers + stage chunk 0 (single bulk copy per batch)
  if (lane == 0){
    mbar_init(barb,     1);
    mbar_init(barb + 8, 1);
  }
  __syncwarp();
  if (lane == 0){
    mbar_expect_tx(barb, 2*CHBYTES);
    bulkcp(sbase,            xg0, CHBYTES, barb);
    bulkcp(sbase + BSTR*4u,  xg1, CHBYTES, barb);
  }

  int buf = 0;
  uint32_t pha0 = 0, pha1 = 0;
  for (int c=0;c<NCH;c++){
    if (lane == 0 && c+1 < NCH){
      uint32_t nb   = barb + (uint32_t)((buf^1)*8);
      uint32_t sb   = sbase + (uint32_t)((buf^1)*BUFF)*4u;
      mbar_expect_tx(nb, 2*CHBYTES);
      bulkcp(sb,            xg0 + (size_t)(c+1)*TS*Ii, CHBYTES, nb);
      bulkcp(sb + BSTR*4u,  xg1 + (size_t)(c+1)*TS*Ii, CHBYTES, nb);
    }
    // wait for current buffer
    if (buf == 0){ mbar_wait(barb,     pha0); pha0 ^= 1; }
    else         { mbar_wait(barb + 8, pha1); pha1 ^= 1; }

    uint32_t xaddr = sbase + (uint32_t)(buf*BUFF + bsub*BSTR)*4u;
    uint32_t bits  = 0;

    #pragma unroll 4
    for (int tt=0; tt<TS; tt++){
      // dense masked dot, both branches: 10 LDS.128 -> 20 ull x-pairs, consumed immediately
      ull p0a, p0b;
      lds128(xaddr, p0a, p0b);
      ull a0 = mul2(wa[0], p0a), a1 = mul2(wa[1], p0b);
      ull q0 = mul2(wb[0], p0a), q1 = mul2(wb[1], p0b);
      #pragma unroll
      for (int j=1;j<10;j++){
        ull xa, xb;
        lds128(xaddr + 16u*j, xa, xb);
        a0 = fma2(wa[2*j],   xa, a0);
        a1 = fma2(wa[2*j+1], xb, a1);
        q0 = fma2(wb[2*j],   xa, q0);
        q1 = fma2(wb[2*j+1], xb, q1);
      }
      float f0,f1;
      ull s0 = add2(a0,a1); upk2(s0,f0,f1); float c0 = f0+f1;   // already scaled by oma*omb0
      ull s1 = add2(q0,q1); upk2(s1,f0,f1); float c1 = f0+f1;

      // recurrence (folded scales): d' = beta*d' + c; mem = alpha*mem + l - asel_prev
      d0 = fmaf(bt.x, d0, c0);
      d1 = fmaf(bt.y, d1, c1);
      float l = d0 + d1;
      mem = fmaf(alpha, mem, l) - asel;
      bool sp = mem > 1.0f;
      asel = sp ? alpha : 0.0f;                      // for next step, off critical path
      bits |= (sp ? 1u : 0u) << tt;                  // pure ALU, no clobber, no cross-lane op

      xaddr += Ii*4;
    }

    // chunk epilogue: 20-ballot transpose -> identical g_masks words as before
    // (ballot bit position = lane = (bsub<<4)|h -> low16 = b0, high16 = b0+1)
    uint32_t m = 0;
    #pragma unroll
    for (int s=0;s<TS;s++){
      uint32_t v = __ballot_sync(0xffffffffu, (bits>>s)&1u);
      if (lane == s) m = v;
    }
    if (lane < TS) mrow[lane] = m;                   // one coalesced STG.32 by lanes 0..19

    mrow += TS;
    buf ^= 1;
  }
}

// ---------------- logits + fast closed-form loss + accuracy ----------------
// thread = one (b,t) point; mask word shared by batch pair (low/high 16 bits).
__global__ void loss_kernel(const int* __restrict__ target, float* __restrict__ out,
                            long long corrIdx){
  // LUTs: logits contribution of each 8-neuron spike sub-mask
  __shared__ float2 lut0[256], lut1[256];
  for (int m = threadIdx.x; m < 256; m += blockDim.x){
    float2 a = make_float2(0.f,0.f), b = make_float2(0.f,0.f);
    #pragma unroll
    for (int j=0;j<8;j++){
      if ((m>>j)&1){
        float2 w = g_w2[j];   a.x += w.x; a.y += w.y;
        float2 v = g_w2[8+j]; b.x += v.x; b.y += v.y;
      }
    }
    lut0[m]=a; lut1[m]=b;
  }
  __syncthreads();

  int idx = blockIdx.x * blockDim.x + threadIdx.x;
  float lossv = 0.f, corr = 0.f;
  if (idx < Bb*Tt){
    int b = idx / Tt;
    int t = idx - b*Tt;
    uint32_t w32 = g_masks[(size_t)(b>>1)*Tt + t];
    uint32_t m16 = (w32 >> ((b&1)<<4)) & 0xFFFFu;
    float2 lo = lut0[m16 & 0xFF];
    float2 hi = lut1[(m16 >> 8) & 0xFF];
    float2 b2v = g_b2c;
    float z0 = lo.x + hi.x + b2v.x;
    float z1 = lo.y + hi.y + b2v.y;
    out[1 + 2*(size_t)idx]     = z0;
    out[1 + 2*(size_t)idx + 1] = z1;
    if ((t>10) && (((t-10)%15)>5)){
      int tgt = target[idx];
      // closed-form double-softmax CE for 2 classes:
      // q = p1-p0 = (e^s-1)/(e^s+1), s = z1-z0
      // loss = ln2 ± q/2 + q^2/8 - q^4/192 + q^6/2880   (|q|<=1, err<3e-5)
      float s  = z1 - z0;
      float e  = __expf(s);
      float r  = __fdividef(1.0f, 1.0f + e);
      float q  = (e - 1.0f) * r;
      float q2 = q*q;
      float even = 0.6931471805599453f
                 + q2*(0.125f + q2*(-5.208333333e-3f + q2*3.472222222e-4f));
      float lossp = even + ((tgt==0) ? 0.5f : -0.5f) * q;
      lossv = lossp * (1.0f/(float)Bb);
      corr  = ((((s>0.0f)?1:0)==tgt)) ? 1.0f : 0.0f;
    }
  }
  #pragma unroll
  for (int off=16; off; off>>=1){
    lossv += __shfl_xor_sync(0xffffffffu, lossv, off);
    corr  += __shfl_xor_sync(0xffffffffu, corr,  off);
  }
  __shared__ float sl[32], sc[32];
  int wq = threadIdx.x>>5, ln = threadIdx.x&31;
  if (ln==0){ sl[wq]=lossv; sc[wq]=corr; }
  __syncthreads();
  if (wq==0){
    int nw = blockDim.x>>5;
    lossv = (ln<nw)? sl[ln]:0.f;
    corr  = (ln<nw)? sc[ln]:0.f;
    #pragma unroll
    for (int off=4; off; off>>=1){
      lossv += __shfl_xor_sync(0xffffffffu,lossv,off);
      corr  += __shfl_xor_sync(0xffffffffu,corr, off);
    }
    if (ln==0){ atomicAdd(out, lossv); atomicAdd(out+corrIdx, corr); }
  }
}

extern "C" void kernel_launch(void* const* d_in, const int* in_sizes, int n_in,
                              void* d_out, int out_size){
  const float* x      = (const float*)d_in[0];
  const int*   target = (const int*)  d_in[1];
  const float* W1     = (const float*)d_in[2];
  const float* tau_m  = (const float*)d_in[3];
  const float* tau_n  = (const float*)d_in[4];
  const float* mask   = (const float*)d_in[5];
  const float* W2     = (const float*)d_in[6];
  const float* b2     = (const float*)d_in[7];
  float* out = (float*)d_out;
  long long corrIdx = (long long)out_size - 2;   // layout: [loss, logits(B*T*2), correct, total]
  long long totIdx  = (long long)out_size - 1;

  init_kernel<<<1, 32>>>(out, corrIdx, totIdx);
  pack_kernel<<<1, 320>>>(W1, tau_m, tau_n, mask, W2, b2);
  snn_kernel<<<Bb/2, 32>>>(x);
  loss_kernel<<<(Bb*Tt + 255)/256, 256>>>(target, out, corrIdx);
}